// round 9
// baseline (speedup 1.0000x reference)
#include <cuda_runtime.h>
#include <cstdint>

#define NN       512
#define NB       16
#define KTOP     50
#define NITERS   100
#define CL       8      // CTAs per cluster (one cluster per batch)
#define RPC      64     // sorted rows owned per CTA
#define NTHREADS 1024   // 32 warps, 2 rows per warp
#define CUT      30.0f  // block-skip threshold in log2 units

__device__ __forceinline__ uint32_t smem_u32(const void* p) {
    return (uint32_t)__cvta_generic_to_shared(p);
}
__device__ __forceinline__ float ex2f_(float x) {
    float r; asm("ex2.approx.ftz.f32 %0, %1;" : "=f"(r) : "f"(x)); return r;
}
__device__ __forceinline__ float lg2f_(float x) {
    float r; asm("lg2.approx.f32 %0, %1;" : "=f"(r) : "f"(x)); return r;
}
// warp-max of a float via order-preserving u32 mapping + redux.sync.max.u32
__device__ __forceinline__ float warp_max_f32(float x) {
    int32_t b = __float_as_int(x);
    uint32_t u = (uint32_t)b ^ (uint32_t)((b >> 31) | 0x80000000);
    uint32_t r;
    asm("redux.sync.max.u32 %0, %1, 0xffffffff;" : "=r"(r) : "r"(u));
    uint32_t bb = r ^ ((~(uint32_t)((int32_t)r >> 31)) | 0x80000000u);
    return __int_as_float((int32_t)bb);
}
__device__ __forceinline__ void cluster_sync_() {
    asm volatile("barrier.cluster.arrive.aligned;" ::: "memory");
    asm volatile("barrier.cluster.wait.aligned;" ::: "memory");
}
__device__ __forceinline__ uint32_t ctarank_() {
    uint32_t r; asm("mov.u32 %0, %%cluster_ctarank;" : "=r"(r)); return r;
}
__device__ __forceinline__ void st_cluster_f32(uint32_t laddr, uint32_t rank, float v) {
    asm volatile(
        "{\n\t.reg .b32 ra;\n\t"
        "mapa.shared::cluster.u32 ra, %0, %1;\n\t"
        "st.shared::cluster.f32 [ra], %2;\n\t}"
        :: "r"(laddr), "r"(rank), "f"(v) : "memory");
}

// One half-step in sorted space: each warp owns 2 rows (one interleaved pair):
//   dst[a] = -lse2_b( M[a,b] + W[b] )
// Pass 1: exact row max over all 512 cols (W register-resident).
// Pass 2: exp-sum over 128-col blocks surviving the CUT, predicated unrolled
// (static register indexing of w[], no W reload).
__device__ __forceinline__ void half_step(
    const float* __restrict__ Msh, const float* __restrict__ Wsh,
    uint32_t dstb, int rowbase, int gbase, int lane)
{
    const float4* W4 = (const float4*)Wsh;
    float w[16];
#pragma unroll
    for (int q = 0; q < 4; q++) {
        float4 t = W4[32 * q + lane];
        w[4*q+0] = t.x; w[4*q+1] = t.y; w[4*q+2] = t.z; w[4*q+3] = t.w;
    }

    const float4* M0 = (const float4*)(Msh + (size_t)rowbase * NN);
    const float4* M1 = (const float4*)(Msh + (size_t)(rowbase + 1) * NN);

    // pass 1: per-block lane maxes of x = M + w
    float mq0[4], mq1[4];
#pragma unroll
    for (int q = 0; q < 4; q++) {
        float4 a = M0[32 * q + lane];
        float4 b = M1[32 * q + lane];
        float a0 = a.x + w[4*q+0], a1 = a.y + w[4*q+1];
        float a2 = a.z + w[4*q+2], a3 = a.w + w[4*q+3];
        float b0 = b.x + w[4*q+0], b1 = b.y + w[4*q+1];
        float b2 = b.z + w[4*q+2], b3 = b.w + w[4*q+3];
        mq0[q] = fmaxf(fmaxf(a0, a1), fmaxf(a2, a3));
        mq1[q] = fmaxf(fmaxf(b0, b1), fmaxf(b2, b3));
    }
    const float m0 = warp_max_f32(fmaxf(fmaxf(mq0[0], mq0[1]), fmaxf(mq0[2], mq0[3])));
    const float m1 = warp_max_f32(fmaxf(fmaxf(mq1[0], mq1[1]), fmaxf(mq1[2], mq1[3])));
    const float c0 = m0 - CUT, c1 = m1 - CUT;

    // active-block mask (warp-uniform); both rows of the pair share it
    unsigned mask = 0;
#pragma unroll
    for (int q = 0; q < 4; q++)
        if (__any_sync(0xffffffffu, (mq0[q] > c0) || (mq1[q] > c1)))
            mask |= 1u << q;

    // pass 2: exp-sum over active blocks (predicated unroll, w in registers)
    float s0a = 0.f, s0b = 0.f, s0c = 0.f, s0d = 0.f;
    float s1a = 0.f, s1b = 0.f, s1c = 0.f, s1d = 0.f;
#pragma unroll
    for (int q = 0; q < 4; q++) {
        if (mask & (1u << q)) {
            float4 a = M0[32 * q + lane];
            float4 b = M1[32 * q + lane];
            s0a += ex2f_((a.x + w[4*q+0]) - m0);
            s0b += ex2f_((a.y + w[4*q+1]) - m0);
            s0c += ex2f_((a.z + w[4*q+2]) - m0);
            s0d += ex2f_((a.w + w[4*q+3]) - m0);
            s1a += ex2f_((b.x + w[4*q+0]) - m1);
            s1b += ex2f_((b.y + w[4*q+1]) - m1);
            s1c += ex2f_((b.z + w[4*q+2]) - m1);
            s1d += ex2f_((b.w + w[4*q+3]) - m1);
        }
    }
    float sum0 = (s0a + s0b) + (s0c + s0d);
    float sum1 = (s1a + s1b) + (s1c + s1d);
#pragma unroll
    for (int o = 16; o > 0; o >>= 1) {
        sum0 += __shfl_xor_sync(0xffffffffu, sum0, o);
        sum1 += __shfl_xor_sync(0xffffffffu, sum1, o);
    }
    const float v0 = -(m0 + lg2f_(sum0));
    const float v1 = -(m1 + lg2f_(sum1));
    if (lane < CL) {
        st_cluster_f32(dstb + (uint32_t)(gbase)     * 4u, (uint32_t)lane, v0);
        st_cluster_f32(dstb + (uint32_t)(gbase + 1) * 4u, (uint32_t)lane, v1);
    }
}

// Sorted coordinate space: t = sort_desc(s), p: sorted pos -> original idx.
// M[a,b] = nk2*(t_a - t_b)^2 (symmetric, band-dominant).
//   step 1:  V[a] = -lse2_b( M[a,b] + U[b] )
//   step 2:  U[a] = -lse2_b( M[a,b] + V[b] )
// out[p[a]] = sum_{j<K} 2^( M[a,j] + U[a] + V[j] )
__global__ void __launch_bounds__(NTHREADS, 1) __cluster_dims__(CL, 1, 1)
sinkhorn_topk_kernel(const float* __restrict__ scores, float* __restrict__ out)
{
    extern __shared__ float Msh[];                 // [RPC][NN] = 128 KB
    __shared__ __align__(16) float t_sh[NN];       // sorted descending
    __shared__ __align__(16) float U_sh[NN];       // row potentials (sorted space)
    __shared__ __align__(16) float V_sh[NN];       // col potentials (sorted space)
    __shared__ int p_sh[NN];                       // sorted pos -> original index

    const int tid   = threadIdx.x;
    const int lane  = tid & 31;
    const int warp  = tid >> 5;
    const int rank  = (int)ctarank_();
    const int batch = blockIdx.x / CL;
    const float nk2 = -1442.6950408889634f;        // -log2(e)/EPSILON

    if (tid < NN) {
        t_sh[tid] = scores[batch * NN + tid];
        p_sh[tid] = tid;
        U_sh[tid] = 0.0f;
        V_sh[tid] = 0.0f;
    }
    __syncthreads();

    // Bitonic sort (value, index) descending — threads 0..511 active
    for (int k = 2; k <= NN; k <<= 1) {
        for (int j = k >> 1; j > 0; j >>= 1) {
            if (tid < NN) {
                int ixj = tid ^ j;
                if (ixj > tid) {
                    float a = t_sh[tid], b = t_sh[ixj];
                    bool desc = ((tid & k) == 0);
                    if (desc ? (a < b) : (a > b)) {
                        t_sh[tid] = b; t_sh[ixj] = a;
                        int pa = p_sh[tid]; p_sh[tid] = p_sh[ixj]; p_sh[ixj] = pa;
                    }
                }
            }
            __syncthreads();
        }
    }

    // Build this CTA's 64 sorted-space rows of M (iteration-invariant)
    {
        const int abase = rank * RPC;
        const int col = tid & (NN - 1);          // 0..511
        const int c0  = (tid >> 9) * (RPC / 2);  // rows 0..31 / 32..63
        const float te = t_sh[col];
#pragma unroll 4
        for (int c = c0; c < c0 + RPC / 2; c++) {
            float d = t_sh[abase + c] - te;
            Msh[c * NN + col] = (d * nk2) * d;
        }
    }
    __syncthreads();
    cluster_sync_();   // all CTAs' U/V init + M done before any peer stores arrive

    const uint32_t Ub = smem_u32(U_sh);
    const uint32_t Vb = smem_u32(V_sh);
    const int rowbase = warp * 2;              // 2 rows per warp
    const int gbase   = rank * RPC + rowbase;  // global sorted row index

    for (int it = 0; it < NITERS; it++) {
        half_step(Msh, U_sh, Vb, rowbase, gbase, lane);   // -> V
        cluster_sync_();
        half_step(Msh, V_sh, Ub, rowbase, gbase, lane);   // -> U
        cluster_sync_();
    }

    // out[p[a]] = sum_{j<K} 2^( nk2*(t_a - t_j)^2 + U[a] + V[j] )
#pragma unroll
    for (int c = 0; c < 2; c++) {
        const int a = gbase + c;
        const float ta = t_sh[a];
        const float ua = U_sh[a];
        float acc = 0.0f;
        for (int jj = lane; jj < KTOP; jj += 32) {
            float d = ta - t_sh[jj];
            acc += ex2f_(fmaf(d * nk2, d, ua + V_sh[jj]));
        }
#pragma unroll
        for (int o = 16; o > 0; o >>= 1)
            acc += __shfl_xor_sync(0xffffffffu, acc, o);
        if (lane == 0) out[batch * NN + p_sh[a]] = acc;
    }
}

extern "C" void kernel_launch(void* const* d_in, const int* in_sizes, int n_in,
                              void* d_out, int out_size) {
    const float* scores = (const float*)d_in[0];
    float* outp = (float*)d_out;
    cudaFuncSetAttribute(sinkhorn_topk_kernel,
                         cudaFuncAttributeMaxDynamicSharedMemorySize,
                         RPC * NN * (int)sizeof(float));
    sinkhorn_topk_kernel<<<NB * CL, NTHREADS, RPC * NN * sizeof(float)>>>(scores, outp);
}

// round 10
// speedup vs baseline: 1.0052x; 1.0052x over previous
#include <cuda_runtime.h>
#include <cstdint>

#define NN       512
#define NB       16
#define KTOP     50
#define NITERS   100
#define CL       8      // CTAs per cluster (one cluster per batch)
#define RPC      64     // sorted rows owned per CTA
#define NTHREADS 1024   // 32 warps, 2 rows per warp
#define CUT      30.0f  // block-skip threshold in log2 units

__device__ __forceinline__ uint32_t smem_u32(const void* p) {
    return (uint32_t)__cvta_generic_to_shared(p);
}
__device__ __forceinline__ float ex2f_(float x) {
    float r; asm("ex2.approx.ftz.f32 %0, %1;" : "=f"(r) : "f"(x)); return r;
}
__device__ __forceinline__ float lg2f_(float x) {
    float r; asm("lg2.approx.f32 %0, %1;" : "=f"(r) : "f"(x)); return r;
}
// warp-max of a float via order-preserving u32 mapping + redux.sync.max.u32
__device__ __forceinline__ float warp_max_f32(float x) {
    int32_t b = __float_as_int(x);
    uint32_t u = (uint32_t)b ^ (uint32_t)((b >> 31) | 0x80000000);
    uint32_t r;
    asm("redux.sync.max.u32 %0, %1, 0xffffffff;" : "=r"(r) : "r"(u));
    uint32_t bb = r ^ ((~(uint32_t)((int32_t)r >> 31)) | 0x80000000u);
    return __int_as_float((int32_t)bb);
}
__device__ __forceinline__ void cluster_sync_() {
    asm volatile("barrier.cluster.arrive.aligned;" ::: "memory");
    asm volatile("barrier.cluster.wait.aligned;" ::: "memory");
}
__device__ __forceinline__ uint32_t ctarank_() {
    uint32_t r; asm("mov.u32 %0, %%cluster_ctarank;" : "=r"(r)); return r;
}
__device__ __forceinline__ void st_cluster_f32(uint32_t laddr, uint32_t rank, float v) {
    asm volatile(
        "{\n\t.reg .b32 ra;\n\t"
        "mapa.shared::cluster.u32 ra, %0, %1;\n\t"
        "st.shared::cluster.f32 [ra], %2;\n\t}"
        :: "r"(laddr), "r"(rank), "f"(v) : "memory");
}

// One half-step in sorted space: each warp owns 2 rows (one interleaved pair):
//   dst[a] = -lse2_b( M[a,b] + W[b] )
// Pass 1: exact row max over all 512 cols (W register-resident).
// Pass 2: exp-sum over 128-col blocks surviving the CUT, predicated unrolled
// (static register indexing of w[], no W reload).
__device__ __forceinline__ void half_step(
    const float* __restrict__ Msh, const float* __restrict__ Wsh,
    uint32_t dstb, int rowbase, int gbase, int lane)
{
    const float4* W4 = (const float4*)Wsh;
    float w[16];
#pragma unroll
    for (int q = 0; q < 4; q++) {
        float4 t = W4[32 * q + lane];
        w[4*q+0] = t.x; w[4*q+1] = t.y; w[4*q+2] = t.z; w[4*q+3] = t.w;
    }

    const float4* M0 = (const float4*)(Msh + (size_t)rowbase * NN);
    const float4* M1 = (const float4*)(Msh + (size_t)(rowbase + 1) * NN);

    // pass 1: per-block lane maxes of x = M + w
    float mq0[4], mq1[4];
#pragma unroll
    for (int q = 0; q < 4; q++) {
        float4 a = M0[32 * q + lane];
        float4 b = M1[32 * q + lane];
        float a0 = a.x + w[4*q+0], a1 = a.y + w[4*q+1];
        float a2 = a.z + w[4*q+2], a3 = a.w + w[4*q+3];
        float b0 = b.x + w[4*q+0], b1 = b.y + w[4*q+1];
        float b2 = b.z + w[4*q+2], b3 = b.w + w[4*q+3];
        mq0[q] = fmaxf(fmaxf(a0, a1), fmaxf(a2, a3));
        mq1[q] = fmaxf(fmaxf(b0, b1), fmaxf(b2, b3));
    }
    const float m0 = warp_max_f32(fmaxf(fmaxf(mq0[0], mq0[1]), fmaxf(mq0[2], mq0[3])));
    const float m1 = warp_max_f32(fmaxf(fmaxf(mq1[0], mq1[1]), fmaxf(mq1[2], mq1[3])));
    const float c0 = m0 - CUT, c1 = m1 - CUT;

    // active-block mask (warp-uniform); both rows of the pair share it
    unsigned mask = 0;
#pragma unroll
    for (int q = 0; q < 4; q++)
        if (__any_sync(0xffffffffu, (mq0[q] > c0) || (mq1[q] > c1)))
            mask |= 1u << q;

    // pass 2: exp-sum over active blocks (predicated unroll, w in registers)
    float s0a = 0.f, s0b = 0.f, s0c = 0.f, s0d = 0.f;
    float s1a = 0.f, s1b = 0.f, s1c = 0.f, s1d = 0.f;
#pragma unroll
    for (int q = 0; q < 4; q++) {
        if (mask & (1u << q)) {
            float4 a = M0[32 * q + lane];
            float4 b = M1[32 * q + lane];
            s0a += ex2f_((a.x + w[4*q+0]) - m0);
            s0b += ex2f_((a.y + w[4*q+1]) - m0);
            s0c += ex2f_((a.z + w[4*q+2]) - m0);
            s0d += ex2f_((a.w + w[4*q+3]) - m0);
            s1a += ex2f_((b.x + w[4*q+0]) - m1);
            s1b += ex2f_((b.y + w[4*q+1]) - m1);
            s1c += ex2f_((b.z + w[4*q+2]) - m1);
            s1d += ex2f_((b.w + w[4*q+3]) - m1);
        }
    }
    float sum0 = (s0a + s0b) + (s0c + s0d);
    float sum1 = (s1a + s1b) + (s1c + s1d);
#pragma unroll
    for (int o = 16; o > 0; o >>= 1) {
        sum0 += __shfl_xor_sync(0xffffffffu, sum0, o);
        sum1 += __shfl_xor_sync(0xffffffffu, sum1, o);
    }
    const float v0 = -(m0 + lg2f_(sum0));
    const float v1 = -(m1 + lg2f_(sum1));
    if (lane < CL) {
        st_cluster_f32(dstb + (uint32_t)(gbase)     * 4u, (uint32_t)lane, v0);
        st_cluster_f32(dstb + (uint32_t)(gbase + 1) * 4u, (uint32_t)lane, v1);
    }
}

// Sorted coordinate space: t = sort_desc(s), p: sorted pos -> original idx.
// M[a,b] = nk2*(t_a - t_b)^2 (symmetric, band-dominant).
//   step 1:  V[a] = -lse2_b( M[a,b] + U[b] )
//   step 2:  U[a] = -lse2_b( M[a,b] + V[b] )
// out[p[a]] = sum_{j<K} 2^( M[a,j] + U[a] + V[j] )
__global__ void __launch_bounds__(NTHREADS, 1) __cluster_dims__(CL, 1, 1)
sinkhorn_topk_kernel(const float* __restrict__ scores, float* __restrict__ out)
{
    extern __shared__ float Msh[];                 // [RPC][NN] = 128 KB
    __shared__ __align__(16) float t_sh[NN];       // sorted descending
    __shared__ __align__(16) float U_sh[NN];       // row potentials (sorted space)
    __shared__ __align__(16) float V_sh[NN];       // col potentials (sorted space)
    __shared__ int p_sh[NN];                       // sorted pos -> original index

    const int tid   = threadIdx.x;
    const int lane  = tid & 31;
    const int warp  = tid >> 5;
    const int rank  = (int)ctarank_();
    const int batch = blockIdx.x / CL;
    const float nk2 = -1442.6950408889634f;        // -log2(e)/EPSILON

    if (tid < NN) {
        t_sh[tid] = scores[batch * NN + tid];
        p_sh[tid] = tid;
        U_sh[tid] = 0.0f;
        V_sh[tid] = 0.0f;
    }
    __syncthreads();

    // Bitonic sort (value, index) descending — threads 0..511 active
    for (int k = 2; k <= NN; k <<= 1) {
        for (int j = k >> 1; j > 0; j >>= 1) {
            if (tid < NN) {
                int ixj = tid ^ j;
                if (ixj > tid) {
                    float a = t_sh[tid], b = t_sh[ixj];
                    bool desc = ((tid & k) == 0);
                    if (desc ? (a < b) : (a > b)) {
                        t_sh[tid] = b; t_sh[ixj] = a;
                        int pa = p_sh[tid]; p_sh[tid] = p_sh[ixj]; p_sh[ixj] = pa;
                    }
                }
            }
            __syncthreads();
        }
    }

    // Build this CTA's 64 sorted-space rows of M (iteration-invariant)
    {
        const int abase = rank * RPC;
        const int col = tid & (NN - 1);          // 0..511
        const int c0  = (tid >> 9) * (RPC / 2);  // rows 0..31 / 32..63
        const float te = t_sh[col];
#pragma unroll 4
        for (int c = c0; c < c0 + RPC / 2; c++) {
            float d = t_sh[abase + c] - te;
            Msh[c * NN + col] = (d * nk2) * d;
        }
    }
    __syncthreads();
    cluster_sync_();   // all CTAs' U/V init + M done before any peer stores arrive

    const uint32_t Ub = smem_u32(U_sh);
    const uint32_t Vb = smem_u32(V_sh);
    const int rowbase = warp * 2;              // 2 rows per warp
    const int gbase   = rank * RPC + rowbase;  // global sorted row index

    for (int it = 0; it < NITERS; it++) {
        half_step(Msh, U_sh, Vb, rowbase, gbase, lane);   // -> V
        cluster_sync_();
        half_step(Msh, V_sh, Ub, rowbase, gbase, lane);   // -> U
        cluster_sync_();
    }

    // out[p[a]] = sum_{j<K} 2^( nk2*(t_a - t_j)^2 + U[a] + V[j] )
#pragma unroll
    for (int c = 0; c < 2; c++) {
        const int a = gbase + c;
        const float ta = t_sh[a];
        const float ua = U_sh[a];
        float acc = 0.0f;
        for (int jj = lane; jj < KTOP; jj += 32) {
            float d = ta - t_sh[jj];
            acc += ex2f_(fmaf(d * nk2, d, ua + V_sh[jj]));
        }
#pragma unroll
        for (int o = 16; o > 0; o >>= 1)
            acc += __shfl_xor_sync(0xffffffffu, acc, o);
        if (lane == 0) out[batch * NN + p_sh[a]] = acc;
    }
}

extern "C" void kernel_launch(void* const* d_in, const int* in_sizes, int n_in,
                              void* d_out, int out_size) {
    const float* scores = (const float*)d_in[0];
    float* outp = (float*)d_out;
    cudaFuncSetAttribute(sinkhorn_topk_kernel,
                         cudaFuncAttributeMaxDynamicSharedMemorySize,
                         RPC * NN * (int)sizeof(float));
    sinkhorn_topk_kernel<<<NB * CL, NTHREADS, RPC * NN * sizeof(float)>>>(scores, outp);
}